// round 9
// baseline (speedup 1.0000x reference)
#include <cuda_runtime.h>
#include <cstdint>

// ---------------------------------------------------------------------------
// CollectAtomTriples: idx_i SORTED int32 [n], values in [0, VMAX). For each
// run (segment) s of equal values (size c, start off) emit all C(c,2) pairs
// (a<b, combinations order), PLANAR FLOAT32 output (harness compares in a
// common float dtype; all values < 2^24 so float32 is exact):
//   out[0:T)=s   out[T:2T)=off+a   out[2T:3T)=off+b
// ---------------------------------------------------------------------------

#define VMAX   65536
#define NCHUNK 256
#define CHUNK  (VMAX / NCHUNK)

__device__ int d_pos[VMAX + 1];        // pos[v] = lower_bound(idx, v)
__device__ int d_triOffV[VMAX + 1];    // exclusive prefix of C(cnt(v),2); [VMAX]=T
__device__ int d_segIdV[VMAX];         // exclusive prefix of present-flag

__device__ int d_chunkTri[NCHUNK];
__device__ int d_chunkFlag[NCHUNK];
__device__ int d_chunkTriOff[NCHUNK];
__device__ int d_chunkFlagOff[NCHUNK];

__global__ void k_pos(const int* __restrict__ idx, int n) {
    int v = blockIdx.x * blockDim.x + threadIdx.x;
    if (v > VMAX) return;
    int lo = 0, hi = n;
    while (lo < hi) {
        int m = (lo + hi) >> 1;
        if (__ldg(&idx[m]) < v) lo = m + 1; else hi = m;
    }
    d_pos[v] = lo;
}

__global__ void k_chunk_sum() {
    int i = threadIdx.x;
    if (i >= NCHUNK) return;
    int tri = 0, fl = 0, base = i * CHUNK;
    for (int j = 0; j < CHUNK; j++) {
        int cnt = d_pos[base + j + 1] - d_pos[base + j];
        tri += cnt * (cnt - 1) / 2;
        fl  += (cnt > 0);
    }
    d_chunkTri[i] = tri;
    d_chunkFlag[i] = fl;
}

__global__ void k_chunk_scan() {
    if (threadIdx.x | blockIdx.x) return;
    int rt = 0, rf = 0;
    for (int i = 0; i < NCHUNK; i++) {
        d_chunkTriOff[i] = rt;  d_chunkFlagOff[i] = rf;
        rt += d_chunkTri[i];    rf += d_chunkFlag[i];
    }
    d_triOffV[VMAX] = rt;    // sentinel = T
}

__global__ void k_fill() {
    int i = threadIdx.x;
    if (i >= NCHUNK) return;
    int rt = d_chunkTriOff[i], rf = d_chunkFlagOff[i], base = i * CHUNK;
    for (int j = 0; j < CHUNK; j++) {
        int v = base + j;
        int cnt = d_pos[v + 1] - d_pos[v];
        d_triOffV[v] = rt;  d_segIdV[v] = rf;
        rt += cnt * (cnt - 1) / 2;
        rf += (cnt > 0);
    }
}

__global__ void k_emit(float* __restrict__ out, int T) {
    int t = blockIdx.x * blockDim.x + threadIdx.x;
    if (t >= T) return;

    // largest v in [0, VMAX-1] with triOffV[v] <= t  -> owning value
    int lo = 0, hi = VMAX - 1;
    #pragma unroll
    for (int step = 0; step < 16; step++) {
        int mid = (lo + hi + 1) >> 1;
        if (__ldg(&d_triOffV[mid]) <= t) lo = mid; else hi = mid - 1;
    }
    int v   = lo;
    int r   = t - __ldg(&d_triOffV[v]);
    int beg = __ldg(&d_pos[v]);
    int c   = __ldg(&d_pos[v + 1]) - beg;
    int s   = __ldg(&d_segIdV[v]);
    int M   = c * (c - 1) / 2;
    int rr  = M - 1 - r;  if (rr < 0) rr = 0;

    // fp32 triangular-root seed + exact integer fix-up
    int a_rev = (int)floorf((sqrtf(8.0f * (float)rr + 1.0f) - 1.0f) * 0.5f);
    if (a_rev < 0) a_rev = 0;
    if ((a_rev + 1) * (a_rev + 2) / 2 <= rr) a_rev++;
    if (a_rev * (a_rev + 1) / 2 > rr)        a_rev--;

    int a = c - 2 - a_rev;
    int b = c - 1 - (rr - a_rev * (a_rev + 1) / 2);

    out[t]         = (float)s;            // all values < 2^24: exact in fp32
    out[T + t]     = (float)(beg + a);
    out[2 * T + t] = (float)(beg + b);
}

// ---------------------------------------------------------------------------
extern "C" void kernel_launch(void* const* d_in, const int* in_sizes, int n_in,
                              void* d_out, int out_size) {
    const int* idx = (const int*)d_in[0];
    int n = in_sizes[0];
    int T = out_size / 3;                 // planar [s | j | k], float32 elements
    float* out = (float*)d_out;

    k_pos<<<(VMAX + 1 + 255) / 256, 256>>>(idx, n);
    k_chunk_sum<<<1, NCHUNK>>>();
    k_chunk_scan<<<1, 1>>>();
    k_fill<<<1, NCHUNK>>>();
    k_emit<<<(T + 255) / 256, 256>>>(out, T);
}

// round 11
// speedup vs baseline: 2.2000x; 2.2000x over previous
#include <cuda_runtime.h>
#include <cstdint>

// ---------------------------------------------------------------------------
// CollectAtomTriples: idx_i SORTED int32 [n], values in [0, VMAX). For each
// run (segment) s of equal values (size c, start off) emit all C(c,2) pairs
// (a<b, combinations order), PLANAR FLOAT32 output (values < 2^24: exact):
//   out[0:T)=s   out[T:2T)=off+a   out[2T:3T)=off+b
// ---------------------------------------------------------------------------

#define VMAX   65536
#define NCHUNK 256
#define CHUNK  256          // VMAX / NCHUNK

__device__ int d_pos[VMAX + 1];       // pos[v] = lower_bound(idx, v)
__device__ int d_triOffV[VMAX + 1];   // exclusive prefix of C(cnt(v),2); [VMAX]=T
__device__ int d_segIdV[VMAX];        // exclusive prefix of present-flag
__device__ int d_chunkTri[NCHUNK];
__device__ int d_chunkFlag[NCHUNK];
__device__ int d_chunkTriOff[NCHUNK];
__device__ int d_chunkFlagOff[NCHUNK];

// ---------------- K1: pos[v] = lower_bound(idx, n, v) ----------------------
__global__ void k_pos(const int* __restrict__ idx, int n) {
    int v = blockIdx.x * blockDim.x + threadIdx.x;
    if (v > VMAX) return;
    int lo = 0, hi = n;
    while (lo < hi) {
        int m = (lo + hi) >> 1;
        if (__ldg(&idx[m]) < v) lo = m + 1; else hi = m;
    }
    d_pos[v] = lo;
}

// packed helpers: tri-count in low 32, flag-count in high 32 (both < 2^31)
__device__ __forceinline__ long long pack2(int fl, int tri) {
    return ((long long)fl << 32) | (unsigned int)tri;
}

// block-wide inclusive scan of packed 64-bit values (blockDim.x = 256)
__device__ __forceinline__ long long block_scan_ll(long long v) {
    const int lane = threadIdx.x & 31;
    const int warp = threadIdx.x >> 5;
    #pragma unroll
    for (int o = 1; o < 32; o <<= 1) {
        long long u = __shfl_up_sync(0xffffffffu, v, o);
        if (lane >= o) v += u;
    }
    __shared__ long long wsum[8];
    if (lane == 31) wsum[warp] = v;
    __syncthreads();
    if (warp == 0) {
        long long w = (lane < 8) ? wsum[lane] : 0;
        #pragma unroll
        for (int o = 1; o < 8; o <<= 1) {
            long long u = __shfl_up_sync(0xffffffffu, w, o);
            if (lane >= o) w += u;
        }
        if (lane < 8) wsum[lane] = w;
    }
    __syncthreads();
    long long add = (warp > 0) ? wsum[warp - 1] : 0;
    return v + add;
}

// ---------------- K2: per-chunk totals (256 blocks x 256 thr) --------------
__global__ void k_sum() {
    int v = blockIdx.x * CHUNK + threadIdx.x;
    int cnt = d_pos[v + 1] - d_pos[v];
    long long p = pack2(cnt > 0, cnt * (cnt - 1) / 2);
    // block reduction via shuffles + shared
    const int lane = threadIdx.x & 31;
    const int warp = threadIdx.x >> 5;
    #pragma unroll
    for (int o = 16; o > 0; o >>= 1)
        p += __shfl_down_sync(0xffffffffu, p, o);
    __shared__ long long ws[8];
    if (lane == 0) ws[warp] = p;
    __syncthreads();
    if (threadIdx.x == 0) {
        long long s = 0;
        #pragma unroll
        for (int w = 0; w < 8; w++) s += ws[w];
        d_chunkTri[blockIdx.x]  = (int)(s & 0xffffffffLL);
        d_chunkFlag[blockIdx.x] = (int)(s >> 32);
    }
}

// ---------------- K3: scan the 256 chunk totals (1 block) ------------------
__global__ void k_scan256() {
    int i = threadIdx.x;
    long long p = pack2(d_chunkFlag[i], d_chunkTri[i]);
    long long incl = block_scan_ll(p);
    long long excl = incl - p;
    d_chunkTriOff[i]  = (int)(excl & 0xffffffffLL);
    d_chunkFlagOff[i] = (int)(excl >> 32);
    if (i == NCHUNK - 1)
        d_triOffV[VMAX] = (int)(incl & 0xffffffffLL);   // sentinel = T
}

// ---------------- K4: per-value prefixes (256 blocks x 256 thr) ------------
__global__ void k_fill() {
    int v = blockIdx.x * CHUNK + threadIdx.x;
    int cnt = d_pos[v + 1] - d_pos[v];
    long long p = pack2(cnt > 0, cnt * (cnt - 1) / 2);
    long long incl = block_scan_ll(p);
    long long excl = incl - p;
    d_triOffV[v] = d_chunkTriOff[blockIdx.x]  + (int)(excl & 0xffffffffLL);
    d_segIdV[v]  = d_chunkFlagOff[blockIdx.x] + (int)(excl >> 32);
}

// ---------------- K5: emit, 4 triples per thread ---------------------------
__global__ void k_emit(float* __restrict__ out, int T) {
    int t0 = (blockIdx.x * blockDim.x + threadIdx.x) * 4;
    if (t0 >= T) return;

    // largest v with triOffV[v] <= t0 (owner of t0)
    int lo = 0, hi = VMAX - 1;
    #pragma unroll
    for (int step = 0; step < 16; step++) {
        int mid = (lo + hi + 1) >> 1;
        if (__ldg(&d_triOffV[mid]) <= t0) lo = mid; else hi = mid - 1;
    }
    int v       = lo;
    int off     = __ldg(&d_triOffV[v]);
    int nextOff = __ldg(&d_triOffV[v + 1]);
    int beg     = __ldg(&d_pos[v]);
    int c       = __ldg(&d_pos[v + 1]) - beg;
    int s       = __ldg(&d_segIdV[v]);
    int M       = c * (c - 1) / 2;

    #pragma unroll
    for (int k = 0; k < 4; k++) {
        int t = t0 + k;
        if (t >= T) break;
        while (t >= nextOff) {          // advance owner (skips empty values)
            v++;
            off = nextOff;
            nextOff = __ldg(&d_triOffV[v + 1]);
            beg = __ldg(&d_pos[v]);
            c   = __ldg(&d_pos[v + 1]) - beg;
            s   = __ldg(&d_segIdV[v]);
            M   = c * (c - 1) / 2;
        }
        int r  = t - off;
        int rr = M - 1 - r;
        int a_rev = (int)floorf((sqrtf(8.0f * (float)rr + 1.0f) - 1.0f) * 0.5f);
        if (a_rev < 0) a_rev = 0;
        if ((a_rev + 1) * (a_rev + 2) / 2 <= rr) a_rev++;
        if (a_rev * (a_rev + 1) / 2 > rr)        a_rev--;
        int a = c - 2 - a_rev;
        int b = c - 1 - (rr - a_rev * (a_rev + 1) / 2);

        out[t]         = (float)s;
        out[T + t]     = (float)(beg + a);
        out[2 * T + t] = (float)(beg + b);
    }
}

// ---------------------------------------------------------------------------
extern "C" void kernel_launch(void* const* d_in, const int* in_sizes, int n_in,
                              void* d_out, int out_size) {
    const int* idx = (const int*)d_in[0];
    int n = in_sizes[0];
    int T = out_size / 3;                 // planar [s | j | k], float32
    float* out = (float*)d_out;

    k_pos<<<(VMAX + 1 + 255) / 256, 256>>>(idx, n);
    k_sum<<<NCHUNK, CHUNK>>>();
    k_scan256<<<1, NCHUNK>>>();
    k_fill<<<NCHUNK, CHUNK>>>();
    int threads = (T + 3) / 4;
    k_emit<<<(threads + 255) / 256, 256>>>(out, T);
}